// round 4
// baseline (speedup 1.0000x reference)
#include <cuda_runtime.h>
#include <stdint.h>

#define NB 256
#define LL 1024
#define TT 128
#define TSTRIDE 129          // padded row stride (floats) -> conflict-free smem rows
#define THREADS 128
#define FULL 0xffffffffu

// dynamic smem layout (bytes)
#define OFF_TRANST 0                                   // 128*129*4 = 66048
#define OFF_BP     (TT * TSTRIDE * 4)                  // 66048, size 1024*128 = 131072
#define OFF_TAGS   (OFF_BP + LL * TT)                  // 197120, size 4096
#define OFF_RED    (OFF_TAGS + LL * 4)                 // 201216, size 2048
#define SMEM_BYTES (OFF_RED + 2048)                    // 203264

// order-preserving float -> uint map (for __reduce_max_sync)
__device__ __forceinline__ unsigned fmap(float f) {
    unsigned u = __float_as_uint(f);
    return (u & 0x80000000u) ? ~u : (u | 0x80000000u);
}
__device__ __forceinline__ float funmap(unsigned u) {
    return __uint_as_float((u & 0x80000000u) ? (u ^ 0x80000000u) : ~u);
}

__global__ __launch_bounds__(THREADS, 1)
void crf_decode_kernel(const float* __restrict__ x,
                       const int* __restrict__ lengths,
                       const float* __restrict__ trans,
                       float* __restrict__ out)          // <-- float32 output
{
    extern __shared__ char smem[];
    float*    s_transT = (float*)(smem + OFF_TRANST);          // [j][i], stride 129
    uint8_t*  s_bp     = (uint8_t*)(smem + OFF_BP);            // [t][j]
    int*      s_tags   = (int*)(smem + OFF_TAGS);
    float*    s_red    = (float*)(smem + OFF_RED);             // [0..127] mx, [128..255] mn
    float*    s_D      = s_red + 256;
    float*    s_state  = s_red + 260;                          // 128 floats
    unsigned* s_wmax   = (unsigned*)(s_state + TT);            // 4
    unsigned* s_mask   = s_wmax + 4;                           // 4

    const int tid  = threadIdx.x;
    const int b    = blockIdx.x;
    const int lane = tid & 31;
    const int w    = tid >> 5;

    int len = lengths[b];
    if (len > LL) len = LL;

    // ---- transpose trans into smem; fold per-thread min/max (thread owns column tid) ----
    {
        float mx = -3.4e38f, mn = 3.4e38f;
        #pragma unroll 4
        for (int i = 0; i < TT; ++i) {
            float v = trans[i * TT + tid];         // coalesced per i
            s_transT[tid * TSTRIDE + i] = v;       // conflict-free (stride 129)
            mx = fmaxf(mx, v);
            mn = fminf(mn, v);
        }
        s_red[tid]       = mx;
        s_red[128 + tid] = mn;
    }

    const float* xb = x + (size_t)b * (LL * TT);
    float sj = xb[tid];                            // state_0[j] = x[b,0,j]
    s_state[tid] = sj;
    __syncthreads();

    if (tid == 0) {
        float gmx = -3.4e38f, gmn = 3.4e38f;
        for (int k = 0; k < TT; ++k) {
            gmx = fmaxf(gmx, s_red[k]);
            gmn = fminf(gmn, s_red[128 + k]);
        }
        float D = (gmx - gmn) * 1.001f + 0.01f;    // exact pruning width + fp margin
        if (!(D >= 0.01f && D <= 1000.0f)) D = 3.0e38f;   // dense fallback
        *s_D = D;
    }
    __syncthreads();
    const float D = *s_D;
    const float* rowT = s_transT + tid * TSTRIDE;

    float xt = (len > 1) ? xb[TT + tid] : 0.0f;    // prefetched x row t=1

    for (int t = 1; t < len; ++t) {
        // block max of state: warp redux on mapped uints, combine via smem
        unsigned wmu = __reduce_max_sync(FULL, fmap(sj));
        if (lane == 0) s_wmax[w] = wmu;
        __syncthreads();                            // BAR1 (also publishes prev state writes)
        unsigned lmu = max(max(s_wmax[0], s_wmax[1]), max(s_wmax[2], s_wmax[3]));
        float thr = funmap(lmu) - D;

        unsigned bal = __ballot_sync(FULL, sj >= thr);
        if (lane == 0) s_mask[w] = bal;
        __syncthreads();                            // BAR2

        unsigned m0 = s_mask[0], m1 = s_mask[1], m2 = s_mask[2], m3 = s_mask[3];
        if ((m0 | m1 | m2 | m3) == 0u) {            // impossible with sane D; dense fallback
            m0 = m1 = m2 = m3 = 0xffffffffu;
        }

        float xn = (t + 1 < len) ? xb[(size_t)(t + 1) * TT + tid] : 0.0f;

        // survivor scan, ascending i -> strict '>' keeps first argmax (reference semantics)
        float best = -3.4e38f;
        int   bi   = 0;
        #pragma unroll
        for (int w2 = 0; w2 < 4; ++w2) {
            unsigned mm = (w2 == 0) ? m0 : (w2 == 1) ? m1 : (w2 == 2) ? m2 : m3;
            while (mm) {
                int l2 = __ffs(mm) - 1; mm &= mm - 1;
                int i  = (w2 << 5) + l2;
                float v = s_state[i] + rowT[i];     // broadcast LDS + conflict-free LDS
                if (v > best) { best = v; bi = i; }
            }
        }

        s_bp[t * TT + tid] = (uint8_t)bi;
        float newsj = best + xt;                    // max + x_t (reference order)
        xt = xn;
        __syncthreads();                            // BAR3: all reads of old state done
        sj = newsj;
        s_state[tid] = sj;
    }
    __syncthreads();                                // publish final state

    // ---- final argmax (first-max) + backward walk: thread 0 ----
    if (tid == 0) {
        float bestf = s_state[0];
        int cand = 0;
        for (int i = 1; i < TT; ++i) {
            float v = s_state[i];
            if (v > bestf) { bestf = v; cand = i; }
        }
        int carry = cand;
        for (int t = len - 1; t >= 1; --t) {
            s_tags[t] = carry;
            carry = (int)s_bp[t * TT + carry];
        }
        s_tags[0] = carry;
    }
    __syncthreads();

    // ---- output: float32 tags for t < len, zeros beyond ----
    float* orow = out + b * LL;
    #pragma unroll 4
    for (int k = tid; k < LL / 4; k += THREADS) {
        int base = k << 2;
        float4 v;
        v.x = (base + 0 < len) ? (float)s_tags[base + 0] : 0.0f;
        v.y = (base + 1 < len) ? (float)s_tags[base + 1] : 0.0f;
        v.z = (base + 2 < len) ? (float)s_tags[base + 2] : 0.0f;
        v.w = (base + 3 < len) ? (float)s_tags[base + 3] : 0.0f;
        ((float4*)orow)[k] = v;
    }
}

extern "C" void kernel_launch(void* const* d_in, const int* in_sizes, int n_in,
                              void* d_out, int out_size)
{
    // Size-based identification (element counts or byte counts); positional fallback.
    const float* x       = nullptr;
    const int*   lengths = nullptr;
    const float* trans   = nullptr;
    for (int i = 0; i < n_in; ++i) {
        long s = in_sizes[i];
        if      (s == 33554432L || s == 134217728L) x       = (const float*)d_in[i];
        else if (s == 256L      || s == 1024L)      lengths = (const int*)d_in[i];
        else if (s == 16384L    || s == 65536L)     trans   = (const float*)d_in[i];
        // 262144 / 1048576 = tags (unused)
    }
    if (!x       && n_in > 0) x       = (const float*)d_in[0];
    if (!lengths && n_in > 1) lengths = (const int*)d_in[1];
    if (!trans   && n_in > 3) trans   = (const float*)d_in[3];

    cudaFuncSetAttribute(crf_decode_kernel,
                         cudaFuncAttributeMaxDynamicSharedMemorySize, SMEM_BYTES);
    crf_decode_kernel<<<NB, THREADS, SMEM_BYTES>>>(x, lengths, trans, (float*)d_out);
}